// round 15
// baseline (speedup 1.0000x reference)
#include <cuda_runtime.h>
#include <cstdint>

#define NNODES_MAX 40000
#define D 128
#define D4 32

// ---------------- device scratch (no allocation allowed) ----------------
__device__ __align__(16) float g_agg[NNODES_MAX * D];
__device__ __align__(16) float g_h1 [NNODES_MAX * D];
__device__ __align__(16) float g_sum[D];
__device__ __align__(16) float g_sq [D];
__device__ __align__(16) float g_w1t[D * D];   // tf32-rounded W1
__device__ __align__(16) float g_w2t[D * D];   // tf32-rounded W2

__device__ __forceinline__ uint32_t f2tf32(float x) {
    uint32_t r; asm("cvt.rna.tf32.f32 %0, %1;" : "=r"(r) : "f"(x)); return r;
}
__device__ __forceinline__ uint32_t smem_u32(const void* p) {
    uint32_t a;
    asm("{ .reg .u64 t; cvta.to.shared.u64 t, %1; cvt.u32.u64 %0, t; }" : "=r"(a) : "l"(p));
    return a;
}
__device__ __forceinline__ void ldm_x4(uint32_t& r0, uint32_t& r1, uint32_t& r2, uint32_t& r3,
                                       uint32_t addr) {
    asm volatile("ldmatrix.sync.aligned.m8n8.x4.shared.b16 {%0,%1,%2,%3}, [%4];"
                 : "=r"(r0), "=r"(r1), "=r"(r2), "=r"(r3) : "r"(addr));
}

// ---------------- W pre-conversion to tf32 ----------------
__global__ void k_cvtW(const float* __restrict__ W1, const float* __restrict__ W2) {
    int i = blockIdx.x * blockDim.x + threadIdx.x;
    if (i < D * D) {
        g_w1t[i] = __uint_as_float(f2tf32(W1[i]));
        g_w2t[i] = __uint_as_float(f2tf32(W2[i]));
    }
}

// ---------------- init: residual scale + zero BN stats (fused) ----------------
__global__ void k_init_agg(const float* __restrict__ x, const float* __restrict__ eps, int n4) {
    int i = blockIdx.x * blockDim.x + threadIdx.x;
    if (blockIdx.x == 0 && threadIdx.x < D) { g_sum[threadIdx.x] = 0.f; g_sq[threadIdx.x] = 0.f; }
    if (i >= n4) return;
    float s = 1.0f + eps[0];
    float4 v = ((const float4*)x)[i];
    v.x *= s; v.y *= s; v.z *= s; v.w *= s;
    ((float4*)g_agg)[i] = v;
}

// ---------------- edge scatter: one warp per edge, vector reduction ----------------
__device__ __forceinline__ void red_add_v4(float* addr, float4 v) {
    asm volatile("red.global.add.v4.f32 [%0], {%1, %2, %3, %4};"
                 :: "l"(addr), "f"(v.x), "f"(v.y), "f"(v.z), "f"(v.w) : "memory");
}

__global__ void k_scatter(const float* __restrict__ x,
                          const int* __restrict__ src,
                          const int* __restrict__ dst, int E, int N) {
    int lane = threadIdx.x & 31;
    int warp = (blockIdx.x * blockDim.x + threadIdx.x) >> 5;
    int nwarps = (gridDim.x * blockDim.x) >> 5;
    for (int e = warp; e < E; e += nwarps) {
        int s = src[e];
        int d = dst[e];
        if ((unsigned)s >= (unsigned)N || (unsigned)d >= (unsigned)N) continue;
        float4 v = ((const float4*)(x + (long long)s * D))[lane];
        v.x = fmaxf(v.x, 0.f); v.y = fmaxf(v.y, 0.f);
        v.z = fmaxf(v.z, 0.f); v.w = fmaxf(v.w, 0.f);
        red_add_v4(g_agg + (long long)d * D + (lane << 2), v);
    }
}

// ---------------- round g_agg in place to tf32 (rna) ----------------
__global__ void k_round_agg(int n4) {
    int i = blockIdx.x * blockDim.x + threadIdx.x;
    if (i >= n4) return;
    float4 v = ((const float4*)g_agg)[i];
    v.x = __uint_as_float(f2tf32(v.x));
    v.y = __uint_as_float(f2tf32(v.y));
    v.z = __uint_as_float(f2tf32(v.z));
    v.w = __uint_as_float(f2tf32(v.w));
    ((float4*)g_agg)[i] = v;
}

// ---------------- BN + ReLU + tf32-round g_h1 in place ----------------
__global__ void k_bnrelu(const float* __restrict__ gamma, const float* __restrict__ beta,
                         int nrows, int n4) {
    __shared__ float sSc[D], sSh[D];
    int t = threadIdx.x;
    if (t < D) {
        float invN = 1.0f / (float)nrows;
        float mu   = g_sum[t] * invN;
        float var  = g_sq[t] * invN - mu * mu;
        float sc   = rsqrtf(var + 1e-5f) * gamma[t];
        sSc[t] = sc;
        sSh[t] = beta[t] - mu * sc;
    }
    __syncthreads();
    int i = blockIdx.x * blockDim.x + t;
    if (i >= n4) return;
    float4 v = ((const float4*)g_h1)[i];
    int k0 = (i & 31) << 2;
    v.x = __uint_as_float(f2tf32(fmaxf(fmaf(v.x, sSc[k0    ], sSh[k0    ]), 0.f)));
    v.y = __uint_as_float(f2tf32(fmaxf(fmaf(v.y, sSc[k0 + 1], sSh[k0 + 1]), 0.f)));
    v.z = __uint_as_float(f2tf32(fmaxf(fmaf(v.z, sSc[k0 + 2], sSh[k0 + 2]), 0.f)));
    v.w = __uint_as_float(f2tf32(fmaxf(fmaf(v.w, sSc[k0 + 3], sSh[k0 + 3]), 0.f)));
    ((float4*)g_h1)[i] = v;
}

// ---------------- tf32 mma.sync GEMM: ldmatrix fragments, cp.async pipeline ----------------
// C[i,j] = sum_k A[i,k]*W[j,k] + bias[j]; A and W pre-rounded to tf32 bits.
// MODE 0: A = g_agg, W = g_w1t -> C = g_h1, fused BN column stats.
// MODE 1: A = g_h1 (already BNReLU'd+rounded), W = g_w2t -> C = out.
__device__ __forceinline__ void mma_tf32(float* c, const uint32_t* a, const uint32_t* b) {
    asm volatile("mma.sync.aligned.m16n8k8.row.col.f32.tf32.tf32.f32 "
                 "{%0,%1,%2,%3}, {%4,%5,%6,%7}, {%8,%9}, {%0,%1,%2,%3};"
                 : "+f"(c[0]), "+f"(c[1]), "+f"(c[2]), "+f"(c[3])
                 : "r"(a[0]), "r"(a[1]), "r"(a[2]), "r"(a[3]), "r"(b[0]), "r"(b[1]));
}

template <int MODE>
__global__ void __launch_bounds__(256, 2) k_gemm_mma(const float* __restrict__ bias,
                                                     float* __restrict__ outp, int nrows) {
    __shared__ float sA[2][128][36];
    __shared__ float sB[2][128][36];

    const float* __restrict__ A  = (MODE == 0) ? g_agg : g_h1;
    const float* __restrict__ Wt = (MODE == 0) ? g_w1t : g_w2t;
    float* __restrict__ Cp       = (MODE == 0) ? g_h1  : outp;

    int tid  = threadIdx.x;
    int wid  = tid >> 5, lane = tid & 31;
    int g    = lane >> 2, t4 = lane & 3;
    int wm   = (wid >> 2) * 64;
    int wn   = (wid & 3) * 32;
    int rowbase = blockIdx.x * 128;

    int rS  = tid >> 3;
    int c4S = tid & 7;

    // ldmatrix per-lane address bases (byte offsets into a [128][36] buffer)
    const uint32_t BUFB = 128u * 36u * 4u;
    uint32_t sAbase = smem_u32(&sA[0][0][0]);
    uint32_t sBbase = smem_u32(&sB[0][0][0]);
    int q = lane >> 3;
    int aRow = ((q & 1) << 3) + (lane & 7);
    int aCol = (q >> 1) << 2;
    uint32_t aOff = (uint32_t)(((wm + aRow) * 36 + aCol) * 4);
    int bRow = ((q >> 1) << 3) + (lane & 7);
    int bCol = (q & 1) << 2;
    uint32_t bOff = (uint32_t)(((wn + bRow) * 36 + bCol) * 4);

    auto issue_chunk = [&](int kc, int buf) {
#pragma unroll
        for (int it = 0; it < 4; ++it) {
            int r = rS + it * 32;
            int grow = rowbase + r;
            uint32_t dstA = smem_u32(&sA[buf][r][c4S * 4]);
            const float* srcA = A + (size_t)grow * D + kc * 32 + c4S * 4;
            int valid = (grow < nrows) ? 16 : 0;
            asm volatile("cp.async.cg.shared.global [%0], [%1], 16, %2;"
                         :: "r"(dstA), "l"(srcA), "r"(valid) : "memory");
            uint32_t dstB = smem_u32(&sB[buf][r][c4S * 4]);
            const float* srcB = Wt + (size_t)r * D + kc * 32 + c4S * 4;
            asm volatile("cp.async.cg.shared.global [%0], [%1], 16;"
                         :: "r"(dstB), "l"(srcB) : "memory");
        }
        asm volatile("cp.async.commit_group;" ::: "memory");
    };

    float acc[4][4][4];
#pragma unroll
    for (int mi = 0; mi < 4; mi++)
#pragma unroll
        for (int nj = 0; nj < 4; nj++)
#pragma unroll
            for (int qq = 0; qq < 4; qq++) acc[mi][nj][qq] = 0.f;

    issue_chunk(0, 0);

    for (int kc = 0; kc < 4; ++kc) {
        int buf = kc & 1;
        asm volatile("cp.async.wait_group 0;" ::: "memory");
        __syncthreads();    // chunk kc visible; all warps past MMA(kc-1) reads of buf^1
        if (kc < 3) issue_chunk(kc + 1, buf ^ 1);   // overlaps MMA(kc)

        uint32_t baseA = sAbase + (uint32_t)buf * BUFB + aOff;
        uint32_t baseB = sBbase + (uint32_t)buf * BUFB + bOff;
#pragma unroll
        for (int ks = 0; ks < 4; ++ks) {
            uint32_t kb = (uint32_t)(ks * 8 * 4);
            uint32_t af[4][4];
#pragma unroll
            for (int mi = 0; mi < 4; mi++)
                ldm_x4(af[mi][0], af[mi][1], af[mi][2], af[mi][3],
                       baseA + (uint32_t)(mi * 16 * 36 * 4) + kb);
            uint32_t bf[4][2];
            ldm_x4(bf[0][0], bf[0][1], bf[1][0], bf[1][1], baseB + kb);
            ldm_x4(bf[2][0], bf[2][1], bf[3][0], bf[3][1],
                   baseB + (uint32_t)(16 * 36 * 4) + kb);
#pragma unroll
            for (int mi = 0; mi < 4; mi++)
#pragma unroll
                for (int nj = 0; nj < 4; nj++)
                    mma_tf32(acc[mi][nj], af[mi], bf[nj]);
        }
    }

    // ---- epilogue: bias add, store, (MODE 0) fused BN column stats ----
    float bj0[4], bj1[4];
#pragma unroll
    for (int nj = 0; nj < 4; nj++) {
        int c = wn + nj * 8 + 2 * t4;
        bj0[nj] = bias[c];
        bj1[nj] = bias[c + 1];
    }

    float s0[4], s1[4], q0[4], q1[4];
#pragma unroll
    for (int nj = 0; nj < 4; nj++) { s0[nj] = s1[nj] = q0[nj] = q1[nj] = 0.f; }

#pragma unroll
    for (int mi = 0; mi < 4; mi++) {
        int r0 = rowbase + wm + mi * 16 + g;
        int r1 = r0 + 8;
#pragma unroll
        for (int nj = 0; nj < 4; nj++) {
            int c = wn + nj * 8 + 2 * t4;
            float v00 = acc[mi][nj][0] + bj0[nj];
            float v01 = acc[mi][nj][1] + bj1[nj];
            float v10 = acc[mi][nj][2] + bj0[nj];
            float v11 = acc[mi][nj][3] + bj1[nj];
            if (r0 < nrows) {
                *(float2*)&Cp[(size_t)r0 * D + c] = make_float2(v00, v01);
                if (MODE == 0) {
                    s0[nj] += v00; s1[nj] += v01;
                    q0[nj] = fmaf(v00, v00, q0[nj]); q1[nj] = fmaf(v01, v01, q1[nj]);
                }
            }
            if (r1 < nrows) {
                *(float2*)&Cp[(size_t)r1 * D + c] = make_float2(v10, v11);
                if (MODE == 0) {
                    s0[nj] += v10; s1[nj] += v11;
                    q0[nj] = fmaf(v10, v10, q0[nj]); q1[nj] = fmaf(v11, v11, q1[nj]);
                }
            }
        }
    }

    if (MODE == 0) {
#pragma unroll
        for (int nj = 0; nj < 4; nj++) {
#pragma unroll
            for (int m = 4; m <= 16; m <<= 1) {
                s0[nj] += __shfl_xor_sync(0xFFFFFFFFu, s0[nj], m);
                s1[nj] += __shfl_xor_sync(0xFFFFFFFFu, s1[nj], m);
                q0[nj] += __shfl_xor_sync(0xFFFFFFFFu, q0[nj], m);
                q1[nj] += __shfl_xor_sync(0xFFFFFFFFu, q1[nj], m);
            }
        }
        if (lane < 4) {
#pragma unroll
            for (int nj = 0; nj < 4; nj++) {
                int c = wn + nj * 8 + 2 * t4;
                atomicAdd(&g_sum[c],     s0[nj]);
                atomicAdd(&g_sum[c + 1], s1[nj]);
                atomicAdd(&g_sq [c],     q0[nj]);
                atomicAdd(&g_sq [c + 1], q1[nj]);
            }
        }
    }
}

// ---------------- launch ----------------
extern "C" void kernel_launch(void* const* d_in, const int* in_sizes, int n_in,
                              void* d_out, int out_size) {
    const float* x     = (const float*)d_in[0];
    const int*   src   = (const int*)d_in[1];
    const int*   dst   = (const int*)d_in[2];
    const float* W1    = (const float*)d_in[3];
    const float* b1    = (const float*)d_in[4];
    const float* gamma = (const float*)d_in[5];
    const float* beta  = (const float*)d_in[6];
    const float* W2    = (const float*)d_in[7];
    const float* b2    = (const float*)d_in[8];
    const float* eps   = (const float*)d_in[9];
    float* out = (float*)d_out;

    int N = in_sizes[0] / D;     // 40000
    int E = in_sizes[1];         // 640000
    int n4 = N * D4;

    k_cvtW<<<(D * D + 255) / 256, 256>>>(W1, W2);
    k_init_agg<<<(n4 + 255) / 256, 256>>>(x, eps, n4);
    k_scatter<<<2048, 256>>>(x, src, dst, E, N);
    k_round_agg<<<(n4 + 255) / 256, 256>>>(n4);

    int gb = (N + 127) / 128;
    k_gemm_mma<0><<<gb, 256>>>(b1, nullptr, N);        // + fused BN stats
    k_bnrelu<<<(n4 + 255) / 256, 256>>>(gamma, beta, N, n4);
    k_gemm_mma<1><<<gb, 256>>>(b2, out, N);
}

// round 16
// speedup vs baseline: 1.0921x; 1.0921x over previous
#include <cuda_runtime.h>
#include <cstdint>

#define NNODES_MAX 40000
#define D 128
#define D4 32

// ---------------- device scratch (no allocation allowed) ----------------
__device__ __align__(16) float g_agg[NNODES_MAX * D];
__device__ __align__(16) float g_h1 [NNODES_MAX * D];
__device__ __align__(16) float g_sum[D];
__device__ __align__(16) float g_sq [D];
__device__ __align__(16) float g_w1t[D * D];   // tf32-rounded W1
__device__ __align__(16) float g_w2t[D * D];   // tf32-rounded W2

__device__ __forceinline__ uint32_t f2tf32(float x) {
    uint32_t r; asm("cvt.rna.tf32.f32 %0, %1;" : "=r"(r) : "f"(x)); return r;
}
__device__ __forceinline__ uint32_t smem_u32(const void* p) {
    uint32_t a;
    asm("{ .reg .u64 t; cvta.to.shared.u64 t, %1; cvt.u32.u64 %0, t; }" : "=r"(a) : "l"(p));
    return a;
}
__device__ __forceinline__ void ldm_x4(uint32_t& r0, uint32_t& r1, uint32_t& r2, uint32_t& r3,
                                       uint32_t addr) {
    asm volatile("ldmatrix.sync.aligned.m8n8.x4.shared.b16 {%0,%1,%2,%3}, [%4];"
                 : "=r"(r0), "=r"(r1), "=r"(r2), "=r"(r3) : "r"(addr));
}

// ---------------- init: residual scale + zero BN stats + W cvt (one launch) ----------------
__global__ void k_init_agg(const float* __restrict__ x, const float* __restrict__ eps,
                           const float* __restrict__ W1, const float* __restrict__ W2, int n4) {
    int i = blockIdx.x * blockDim.x + threadIdx.x;
    if (blockIdx.x == 0 && threadIdx.x < D) { g_sum[threadIdx.x] = 0.f; g_sq[threadIdx.x] = 0.f; }
    if (i < D * D) {
        g_w1t[i] = __uint_as_float(f2tf32(W1[i]));
        g_w2t[i] = __uint_as_float(f2tf32(W2[i]));
    }
    if (i >= n4) return;
    float s = 1.0f + eps[0];
    float4 v = ((const float4*)x)[i];
    v.x *= s; v.y *= s; v.z *= s; v.w *= s;
    ((float4*)g_agg)[i] = v;
}

// ---------------- edge scatter: one warp per edge, vector reduction ----------------
__device__ __forceinline__ void red_add_v4(float* addr, float4 v) {
    asm volatile("red.global.add.v4.f32 [%0], {%1, %2, %3, %4};"
                 :: "l"(addr), "f"(v.x), "f"(v.y), "f"(v.z), "f"(v.w) : "memory");
}

__global__ void k_scatter(const float* __restrict__ x,
                          const int* __restrict__ src,
                          const int* __restrict__ dst, int E, int N) {
    int lane = threadIdx.x & 31;
    int warp = (blockIdx.x * blockDim.x + threadIdx.x) >> 5;
    int nwarps = (gridDim.x * blockDim.x) >> 5;
    for (int e = warp; e < E; e += nwarps) {
        int s = src[e];
        int d = dst[e];
        if ((unsigned)s >= (unsigned)N || (unsigned)d >= (unsigned)N) continue;
        float4 v = ((const float4*)(x + (long long)s * D))[lane];
        v.x = fmaxf(v.x, 0.f); v.y = fmaxf(v.y, 0.f);
        v.z = fmaxf(v.z, 0.f); v.w = fmaxf(v.w, 0.f);
        red_add_v4(g_agg + (long long)d * D + (lane << 2), v);
    }
}

// ---------------- tf32 mma.sync GEMM: ldmatrix fragments + in-register transform ----------------
// C[i,j] = sum_k A[i,k]*W[j,k] + bias[j]; W pre-rounded to tf32 bits.
// MODE 0: A = g_agg (fp32) -> C = g_h1, tf32-round A in registers, fused BN column stats.
// MODE 1: A = g_h1 (fp32) -> C = out, BN+ReLU+round applied in registers post-ldmatrix.
__device__ __forceinline__ void mma_tf32(float* c, const uint32_t* a, const uint32_t* b) {
    asm volatile("mma.sync.aligned.m16n8k8.row.col.f32.tf32.tf32.f32 "
                 "{%0,%1,%2,%3}, {%4,%5,%6,%7}, {%8,%9}, {%0,%1,%2,%3};"
                 : "+f"(c[0]), "+f"(c[1]), "+f"(c[2]), "+f"(c[3])
                 : "r"(a[0]), "r"(a[1]), "r"(a[2]), "r"(a[3]), "r"(b[0]), "r"(b[1]));
}

template <int MODE>
__global__ void __launch_bounds__(256, 2) k_gemm_mma(const float* __restrict__ bias,
                                                     const float* __restrict__ gamma,
                                                     const float* __restrict__ beta,
                                                     float* __restrict__ outp, int nrows) {
    __shared__ float sA[2][128][36];
    __shared__ float sB[2][128][36];
    __shared__ float sScale[128], sShift[128];

    const float* __restrict__ A  = (MODE == 0) ? g_agg : g_h1;
    const float* __restrict__ Wt = (MODE == 0) ? g_w1t : g_w2t;
    float* __restrict__ Cp       = (MODE == 0) ? g_h1  : outp;

    int tid  = threadIdx.x;
    int wid  = tid >> 5, lane = tid & 31;
    int g    = lane >> 2, t4 = lane & 3;
    int wm   = (wid >> 2) * 64;
    int wn   = (wid & 3) * 32;
    int rowbase = blockIdx.x * 128;

    if (MODE == 1 && tid < D) {
        float invN = 1.0f / (float)nrows;
        float mu   = g_sum[tid] * invN;
        float var  = g_sq[tid] * invN - mu * mu;
        float sc   = rsqrtf(var + 1e-5f) * gamma[tid];
        sScale[tid] = sc;
        sShift[tid] = beta[tid] - mu * sc;
    }

    int rS  = tid >> 3;
    int c4S = tid & 7;

    // ldmatrix per-lane addresses (validated in R15: reg i <-> mma fragment slot i)
    const uint32_t BUFB = 128u * 36u * 4u;
    uint32_t sAbase = smem_u32(&sA[0][0][0]);
    uint32_t sBbase = smem_u32(&sB[0][0][0]);
    int q = lane >> 3;
    int aRow = ((q & 1) << 3) + (lane & 7);
    int aCol = (q >> 1) << 2;
    uint32_t aOff = (uint32_t)(((wm + aRow) * 36 + aCol) * 4);
    int bRow = ((q >> 1) << 3) + (lane & 7);
    int bCol = (q & 1) << 2;
    uint32_t bOff = (uint32_t)(((wn + bRow) * 36 + bCol) * 4);

    auto issue_chunk = [&](int kc, int buf) {
#pragma unroll
        for (int it = 0; it < 4; ++it) {
            int r = rS + it * 32;
            int grow = rowbase + r;
            uint32_t dstA = smem_u32(&sA[buf][r][c4S * 4]);
            const float* srcA = A + (size_t)grow * D + kc * 32 + c4S * 4;
            int valid = (grow < nrows) ? 16 : 0;
            asm volatile("cp.async.cg.shared.global [%0], [%1], 16, %2;"
                         :: "r"(dstA), "l"(srcA), "r"(valid) : "memory");
            uint32_t dstB = smem_u32(&sB[buf][r][c4S * 4]);
            const float* srcB = Wt + (size_t)r * D + kc * 32 + c4S * 4;
            asm volatile("cp.async.cg.shared.global [%0], [%1], 16;"
                         :: "r"(dstB), "l"(srcB) : "memory");
        }
        asm volatile("cp.async.commit_group;" ::: "memory");
    };

    float acc[4][4][4];
#pragma unroll
    for (int mi = 0; mi < 4; mi++)
#pragma unroll
        for (int nj = 0; nj < 4; nj++)
#pragma unroll
            for (int qq = 0; qq < 4; qq++) acc[mi][nj][qq] = 0.f;

    issue_chunk(0, 0);

    for (int kc = 0; kc < 4; ++kc) {
        int buf = kc & 1;
        asm volatile("cp.async.wait_group 0;" ::: "memory");
        __syncthreads();    // chunk kc visible (covers sScale/sShift on kc=0)
        if (kc < 3) issue_chunk(kc + 1, buf ^ 1);   // overlaps MMA(kc)

        uint32_t baseA = sAbase + (uint32_t)buf * BUFB + aOff;
        uint32_t baseB = sBbase + (uint32_t)buf * BUFB + bOff;
#pragma unroll
        for (int ks = 0; ks < 4; ++ks) {
            uint32_t kb = (uint32_t)(ks * 8 * 4);
            float sc0 = 0.f, sh0 = 0.f, sc1 = 0.f, sh1 = 0.f;
            if (MODE == 1) {
                int kw = kc * 32 + ks * 8;
                sc0 = sScale[kw + t4];     sh0 = sShift[kw + t4];
                sc1 = sScale[kw + t4 + 4]; sh1 = sShift[kw + t4 + 4];
            }
            uint32_t af[4][4];
#pragma unroll
            for (int mi = 0; mi < 4; mi++) {
                ldm_x4(af[mi][0], af[mi][1], af[mi][2], af[mi][3],
                       baseA + (uint32_t)(mi * 16 * 36 * 4) + kb);
                if (MODE == 0) {
                    af[mi][0] = f2tf32(__uint_as_float(af[mi][0]));
                    af[mi][1] = f2tf32(__uint_as_float(af[mi][1]));
                    af[mi][2] = f2tf32(__uint_as_float(af[mi][2]));
                    af[mi][3] = f2tf32(__uint_as_float(af[mi][3]));
                } else {
                    af[mi][0] = f2tf32(fmaxf(fmaf(__uint_as_float(af[mi][0]), sc0, sh0), 0.f));
                    af[mi][1] = f2tf32(fmaxf(fmaf(__uint_as_float(af[mi][1]), sc0, sh0), 0.f));
                    af[mi][2] = f2tf32(fmaxf(fmaf(__uint_as_float(af[mi][2]), sc1, sh1), 0.f));
                    af[mi][3] = f2tf32(fmaxf(fmaf(__uint_as_float(af[mi][3]), sc1, sh1), 0.f));
                }
            }
            uint32_t bf[4][2];
            ldm_x4(bf[0][0], bf[0][1], bf[1][0], bf[1][1], baseB + kb);
            ldm_x4(bf[2][0], bf[2][1], bf[3][0], bf[3][1],
                   baseB + (uint32_t)(16 * 36 * 4) + kb);
#pragma unroll
            for (int mi = 0; mi < 4; mi++)
#pragma unroll
                for (int nj = 0; nj < 4; nj++)
                    mma_tf32(acc[mi][nj], af[mi], bf[nj]);
        }
    }

    // ---- epilogue: bias add, store, (MODE 0) fused BN column stats ----
    float bj0[4], bj1[4];
#pragma unroll
    for (int nj = 0; nj < 4; nj++) {
        int c = wn + nj * 8 + 2 * t4;
        bj0[nj] = bias[c];
        bj1[nj] = bias[c + 1];
    }

    float s0[4], s1[4], q0[4], q1[4];
#pragma unroll
    for (int nj = 0; nj < 4; nj++) { s0[nj] = s1[nj] = q0[nj] = q1[nj] = 0.f; }

#pragma unroll
    for (int mi = 0; mi < 4; mi++) {
        int r0 = rowbase + wm + mi * 16 + g;
        int r1 = r0 + 8;
#pragma unroll
        for (int nj = 0; nj < 4; nj++) {
            int c = wn + nj * 8 + 2 * t4;
            float v00 = acc[mi][nj][0] + bj0[nj];
            float v01 = acc[mi][nj][1] + bj1[nj];
            float v10 = acc[mi][nj][2] + bj0[nj];
            float v11 = acc[mi][nj][3] + bj1[nj];
            if (r0 < nrows) {
                *(float2*)&Cp[(size_t)r0 * D + c] = make_float2(v00, v01);
                if (MODE == 0) {
                    s0[nj] += v00; s1[nj] += v01;
                    q0[nj] = fmaf(v00, v00, q0[nj]); q1[nj] = fmaf(v01, v01, q1[nj]);
                }
            }
            if (r1 < nrows) {
                *(float2*)&Cp[(size_t)r1 * D + c] = make_float2(v10, v11);
                if (MODE == 0) {
                    s0[nj] += v10; s1[nj] += v11;
                    q0[nj] = fmaf(v10, v10, q0[nj]); q1[nj] = fmaf(v11, v11, q1[nj]);
                }
            }
        }
    }

    if (MODE == 0) {
#pragma unroll
        for (int nj = 0; nj < 4; nj++) {
#pragma unroll
            for (int m = 4; m <= 16; m <<= 1) {
                s0[nj] += __shfl_xor_sync(0xFFFFFFFFu, s0[nj], m);
                s1[nj] += __shfl_xor_sync(0xFFFFFFFFu, s1[nj], m);
                q0[nj] += __shfl_xor_sync(0xFFFFFFFFu, q0[nj], m);
                q1[nj] += __shfl_xor_sync(0xFFFFFFFFu, q1[nj], m);
            }
        }
        if (lane < 4) {
#pragma unroll
            for (int nj = 0; nj < 4; nj++) {
                int c = wn + nj * 8 + 2 * t4;
                atomicAdd(&g_sum[c],     s0[nj]);
                atomicAdd(&g_sum[c + 1], s1[nj]);
                atomicAdd(&g_sq [c],     q0[nj]);
                atomicAdd(&g_sq [c + 1], q1[nj]);
            }
        }
    }
}

// ---------------- launch ----------------
extern "C" void kernel_launch(void* const* d_in, const int* in_sizes, int n_in,
                              void* d_out, int out_size) {
    const float* x     = (const float*)d_in[0];
    const int*   src   = (const int*)d_in[1];
    const int*   dst   = (const int*)d_in[2];
    const float* W1    = (const float*)d_in[3];
    const float* b1    = (const float*)d_in[4];
    const float* gamma = (const float*)d_in[5];
    const float* beta  = (const float*)d_in[6];
    const float* W2    = (const float*)d_in[7];
    const float* b2    = (const float*)d_in[8];
    const float* eps   = (const float*)d_in[9];
    float* out = (float*)d_out;

    int N = in_sizes[0] / D;     // 40000
    int E = in_sizes[1];         // 640000
    int n4 = N * D4;

    k_init_agg<<<(n4 + 255) / 256, 256>>>(x, eps, W1, W2, n4);
    k_scatter<<<2048, 256>>>(x, src, dst, E, N);

    int gb = (N + 127) / 128;
    k_gemm_mma<0><<<gb, 256>>>(b1, nullptr, nullptr, nullptr, N);  // + fused BN stats
    k_gemm_mma<1><<<gb, 256>>>(b2, gamma, beta, out, N);           // BN in registers
}